// round 7
// baseline (speedup 1.0000x reference)
#include <cuda_runtime.h>
#include <math.h>

// Scratch: tiled intermediate (B*M*N floats = 134 MB).
#define SCRATCH_ELEMS (2ull * 4096ull * 4096ull)
__device__ float g_scratch[SCRATCH_ELEMS];

#define NN 4096
#define HH 2048

__device__ __forceinline__ float2 cadd(float2 a, float2 b){ return make_float2(a.x+b.x, a.y+b.y); }
__device__ __forceinline__ float2 csub(float2 a, float2 b){ return make_float2(a.x-b.x, a.y-b.y); }
__device__ __forceinline__ float2 cmul(float2 a, float2 b){
    return make_float2(fmaf(a.x, b.x, -a.y*b.y), fmaf(a.x, b.y, a.y*b.x));
}
__device__ __forceinline__ float2 mulip(float2 a){ return make_float2(-a.y, a.x); }  // * (+i)

// Pad one float2 every 16.
#define PIDX(a) ((a) + ((a) >> 4))

// ---- 16-point inverse DFT in registers ----
__device__ __forceinline__ void r16_bfly(float2 g[16]) {
    const float C8 = 0.70710678118654752f;
    const float2 W1 = make_float2( 0.92387953251128674f,  0.38268343236508978f);
    const float2 W2 = make_float2( C8,  C8);
    const float2 W3 = make_float2( 0.38268343236508978f,  0.92387953251128674f);
    const float2 W6 = make_float2(-C8,  C8);
    const float2 W9 = make_float2(-0.92387953251128674f, -0.38268343236508978f);
    float2 c[16];
#pragma unroll
    for (int t0 = 0; t0 < 4; t0++) {
        float2 x0 = g[t0], x1 = g[t0+4], x2 = g[t0+8], x3 = g[t0+12];
        float2 s02 = cadd(x0,x2), d02 = csub(x0,x2);
        float2 s13 = cadd(x1,x3), d13 = csub(x1,x3);
        float2 id13 = mulip(d13);
        c[t0*4+0] = cadd(s02,s13);
        c[t0*4+1] = cadd(d02,id13);
        c[t0*4+2] = csub(s02,s13);
        c[t0*4+3] = csub(d02,id13);
    }
    c[5]  = cmul(c[5],  W1);
    c[6]  = cmul(c[6],  W2);
    c[7]  = cmul(c[7],  W3);
    c[9]  = cmul(c[9],  W2);
    c[10] = mulip(c[10]);
    c[11] = cmul(c[11], W6);
    c[13] = cmul(c[13], W3);
    c[14] = cmul(c[14], W6);
    c[15] = cmul(c[15], W9);
#pragma unroll
    for (int u0 = 0; u0 < 4; u0++) {
        float2 x0 = c[u0], x1 = c[4+u0], x2 = c[8+u0], x3 = c[12+u0];
        float2 s02 = cadd(x0,x2), d02 = csub(x0,x2);
        float2 s13 = cadd(x1,x3), d13 = csub(x1,x3);
        float2 id13 = mulip(d13);
        g[u0]    = cadd(s02,s13);
        g[u0+4]  = cadd(d02,id13);
        g[u0+8]  = csub(s02,s13);
        g[u0+12] = csub(d02,id13);
    }
}

// ---- 8-point inverse DFT in registers ----
__device__ __forceinline__ void r8_bfly(float2 a[8]) {
    const float C8 = 0.70710678118654752f;
    float2 e0 = cadd(a[0],a[4]), e1 = cadd(a[1],a[5]);
    float2 e2 = cadd(a[2],a[6]), e3 = cadd(a[3],a[7]);
    float2 o0 = csub(a[0],a[4]), o1 = csub(a[1],a[5]);
    float2 o2 = csub(a[2],a[6]), o3 = csub(a[3],a[7]);
    o1 = make_float2(C8*(o1.x - o1.y),  C8*(o1.x + o1.y));
    o2 = mulip(o2);
    o3 = make_float2(-C8*(o3.x + o3.y), C8*(o3.x - o3.y));
    float2 t0 = cadd(e0,e2), t1 = csub(e0,e2);
    float2 t2 = cadd(e1,e3), t3 = csub(e1,e3);
    float2 it3 = mulip(t3);
    float2 u0 = cadd(o0,o2), u1 = csub(o0,o2);
    float2 u2 = cadd(o1,o3), u3 = csub(o1,o3);
    float2 iu3 = mulip(u3);
    a[0] = cadd(t0,t2);  a[4] = csub(t0,t2);
    a[2] = cadd(t1,it3); a[6] = csub(t1,it3);
    a[1] = cadd(u0,u2);  a[5] = csub(u0,u2);
    a[3] = cadd(u1,iu3); a[7] = csub(u1,iu3);
}

// ===========================================================================
// Pass 1: IDCT along M on columns of row-major x. 8 cols/CTA, 1024 threads,
// r8/r8/r8/r4 in-place chain. Output: TILED layout T[cgroup][m][dc],
// block of 32768 contiguous floats per cgroup -> fully coalesced store.
// ===========================================================================
#define CSTRIDE_F 4356   // == 4 mod 32 (bank hygiene for this kernel)
#define NCOLS 8

template <int S>
__device__ __forceinline__ void r8_stage_ip(float2* zb, int t) {
    float2 A[2][8];
#pragma unroll
    for (int h = 0; h < 2; h++) {
        const int idx = t + 128*h;
#pragma unroll
        for (int u = 0; u < 8; u++) A[h][u] = zb[PIDX(idx + 256*u)];
    }
    __syncthreads();
#pragma unroll
    for (int h = 0; h < 2; h++) {
        const int idx = t + 128*h;
        r8_bfly(A[h]);
        const int p = idx / S, j = idx - p*S;
        float sn, cs;
        __sincosf((float)(2.0*M_PI*(double)S/2048.0) * (float)p, &sn, &cs);
        const float2 w1 = make_float2(cs, sn);
        const int ob = j + 8*S*p;
        zb[PIDX(ob)] = A[h][0];
        float2 wu = w1;
#pragma unroll
        for (int u = 1; u < 8; u++) {
            zb[PIDX(ob + u*S)] = cmul(A[h][u], wu);
            wu = cmul(wu, w1);
        }
    }
    __syncthreads();
}

__global__ __launch_bounds__(1024, 1)
void idct_col_kernel(const float* __restrict__ in,
                     const float2* __restrict__ expk,
                     float* __restrict__ out_tiled) {
    extern __shared__ __align__(16) float smf[];
    const int tid = threadIdx.x;
    const int b  = blockIdx.x >> 9;           // 512 CTAs per batch
    const int cg = blockIdx.x & 511;
    const int c0 = cg << 3;
    const size_t inbase = (size_t)b * (size_t)NN * (size_t)NN + (size_t)c0;

    // ---- load 8 columns (strided; 32B granule — the one uncoalesced phase) ----
    {
        const int cc = tid & 3;                // float2 column-pair
        const int r0 = tid >> 2;               // 0..255
        const float2* inp2 = (const float2*)(in + inbase);
        float* xsA = smf + (2*cc)     * CSTRIDE_F;
        float* xsB = smf + (2*cc + 1) * CSTRIDE_F;
#pragma unroll
        for (int k = 0; k < 16; k++) {
            const int r = r0 + 256*k;
            const float2 v = inp2[(size_t)r * (NN/2) + cc];
            xsA[r] = v.x;
            xsB[r] = v.y;
        }
    }
    __syncthreads();

    const int t = tid & 127;
    const int c = tid >> 7;                    // 0..7
    float* xs = smf + c * CSTRIDE_F;
    float2* zb = (float2*)xs;

    // ---- prologue: G (IDCT form), registers ----
    float2 G[16];
    {
        const float2 STEP = make_float2(0.98078528040323044f, 0.19509032201612827f); // e^{2pi i/32}
        float sn, cs;
        __sincosf((float)(2.0*M_PI/4096.0) * (float)t, &sn, &cs);
        float2 w = make_float2(cs, sn);
#pragma unroll
        for (int k = 0; k < 16; k++) {
            const int j = t + 128*k;
            const float Xa0 = xs[j];
            const float Xb0 = (j == 0) ? 0.0f : xs[NN - j];
            const float Xa1 = xs[j + HH];
            const float Xb1 = xs[(j == 0) ? HH : (HH - j)];
            const float2 ea = expk[j];
            const float2 eb = expk[j + HH];
            float2 V0 = make_float2(0.5f*(Xa0*ea.x + Xb0*ea.y),
                                    0.5f*(Xa0*ea.y - Xb0*ea.x));
            float2 V1 = make_float2(0.5f*(Xa1*eb.x + Xb1*eb.y),
                                    0.5f*(Xa1*eb.y - Xb1*eb.x));
            float2 S = cadd(V0, V1);
            float2 D = csub(V0, V1);
            float2 wd = cmul(w, D);
            G[k] = make_float2(S.x - wd.y, S.y + wd.x);
            w = cmul(w, STEP);
        }
    }
    __syncthreads();

    // ---- stage 1: radix-8, S=1 from G ----
#pragma unroll
    for (int h = 0; h < 2; h++) {
        float2 a[8];
#pragma unroll
        for (int u = 0; u < 8; u++) a[u] = G[h + 2*u];
        r8_bfly(a);
        const int idx = t + 128*h;
        float sn, cs;
        __sincosf((float)(2.0*M_PI/2048.0) * (float)idx, &sn, &cs);
        const float2 w1 = make_float2(cs, sn);
        zb[PIDX(8*idx)] = a[0];
        float2 wu = w1;
#pragma unroll
        for (int u = 1; u < 8; u++) {
            zb[PIDX(8*idx + u)] = cmul(a[u], wu);
            wu = cmul(wu, w1);
        }
    }
    __syncthreads();

    r8_stage_ip<8>(zb, t);
    r8_stage_ip<64>(zb, t);

    // ---- stage 4: radix-4, S=512, per-thread private slots ----
#pragma unroll
    for (int h = 0; h < 4; h++) {
        const int idx = t + 128*h;
        float2 a0 = zb[PIDX(idx)],        a1 = zb[PIDX(idx + 512)];
        float2 a2 = zb[PIDX(idx + 1024)], a3 = zb[PIDX(idx + 1536)];
        float2 t0 = cadd(a0,a2), t1 = csub(a0,a2);
        float2 t2 = cadd(a1,a3), t3 = csub(a1,a3);
        float2 it3 = mulip(t3);
        zb[PIDX(idx)]        = cadd(t0,t2);
        zb[PIDX(idx + 512)]  = cadd(t1,it3);
        zb[PIDX(idx + 1024)] = csub(t0,t2);
        zb[PIDX(idx + 1536)] = csub(t1,it3);
    }
    __syncthreads();

    // ---- store to TILED layout: fully coalesced float4 ----
    {
        float* ot = out_tiled + (size_t)b * (size_t)NN * (size_t)NN
                              + (size_t)cg * 32768;
#pragma unroll
        for (int k = 0; k < 8; k++) {
            const int o = tid*4 + k*4096;
            const int m = o >> 3;              // output row index
            const int dc4 = o & 7;             // 0 or 4
            const int vidx = (m & 1) ? (4095 - (m >> 1)) : (m >> 1);
            const int s = vidx >> 1;
            const int sel = vidx & 1;
            float v[4];
#pragma unroll
            for (int i = 0; i < 4; i++) {
                const float2* zc = (const float2*)(smf + (dc4 + i) * CSTRIDE_F);
                const float2 z = zc[PIDX(s)];
                v[i] = sel ? z.y : z.x;
            }
            *(float4*)(ot + o) = make_float4(v[0], v[1], v[2], v[3]);
        }
    }
}

// ===========================================================================
// Pass 2: IDXST along N on rows. Input = tiled layout, output = row-major.
// 4 rows/CTA, 512 threads (128/row), in-place single buffer per row,
// radix 16/16/8 (2 shared round-trips), fully coalesced load AND store.
// ===========================================================================
#define CSTRIDE2_F 4360   // == 8 mod 32: tiled-load smem scatter conflict-free

__global__ __launch_bounds__(512, 1)
void idxst_row_kernel(const float* __restrict__ in_tiled,
                      const float2* __restrict__ expk,
                      float* __restrict__ out) {
    extern __shared__ __align__(16) float smf[];
    const int tid = threadIdx.x;
    const int b  = blockIdx.x >> 10;          // 1024 CTAs per batch
    const int m0 = (blockIdx.x & 1023) << 2;  // 4 rows per CTA
    const size_t tbase = (size_t)b * (size_t)NN * (size_t)NN;

    // ---- load from tiled: per cgroup-block a 128B contiguous chunk ----
    {
        const float4* it4 = (const float4*)(in_tiled + tbase);
        const int m0q = m0 * 2;                // (m0*8)/4
#pragma unroll
        for (int k = 0; k < 8; k++) {
            const int idx = tid + 512*k;       // 0..4095
            const int cblk = idx >> 3;
            const int q4 = (idx & 7) * 4;      // float offset in 32-float chunk
            const int m_off = q4 >> 3;
            const int dc4 = q4 & 7;            // 0 or 4
            const float4 v = it4[cblk*8192 + m0q + (q4 >> 2)];
            float* dst = smf + m_off * CSTRIDE2_F + cblk*8 + dc4;
            *(float4*)dst = v;
        }
    }
    __syncthreads();

    const int t = tid & 127;
    const int r = tid >> 7;                    // 0..3
    float* xs = smf + r * CSTRIDE2_F;
    float2* zb = (float2*)xs;

    // ---- stage A: IDXST prologue (registers) + radix-16 + twiddle ----
    {
        float2 g[16];
        const float2 E32 = make_float2(0.98078528040323044f, 0.19509032201612827f);
        float sn, cs;
        __sincosf((float)(2.0*M_PI/4096.0) * (float)t, &sn, &cs);
        float2 w = make_float2(cs, sn);
#pragma unroll
        for (int k = 0; k < 16; k++) {
            const int j = t + 128*k;
            const float Xa0 = (j == 0) ? 0.0f : xs[NN - j];
            const float Xb0 = (j == 0) ? 0.0f : xs[j];
            const float Xa1 = xs[(j == 0) ? HH : (HH - j)];
            const float Xb1 = xs[j + HH];
            const float2 ea = expk[j];
            const float2 eb = expk[j + HH];
            float2 V0 = make_float2(0.5f*(Xa0*ea.x + Xb0*ea.y),
                                    0.5f*(Xa0*ea.y - Xb0*ea.x));
            float2 V1 = make_float2(0.5f*(Xa1*eb.x + Xb1*eb.y),
                                    0.5f*(Xa1*eb.y - Xb1*eb.x));
            float2 S = cadd(V0, V1);
            float2 D = csub(V0, V1);
            float2 wd = cmul(w, D);
            g[k] = make_float2(S.x - wd.y, S.y + wd.x);
            w = cmul(w, E32);
        }
        r16_bfly(g);
        __sincosf((float)(2.0*M_PI/2048.0) * (float)t, &sn, &cs);
        const float2 w1 = make_float2(cs, sn);
        __syncthreads();                       // all xs reads done (in-place)
        zb[PIDX(16*t)] = g[0];
        float2 wu = w1;
#pragma unroll
        for (int u = 1; u < 16; u++) {
            zb[PIDX(16*t + u)] = cmul(g[u], wu);
            wu = cmul(wu, w1);
        }
    }
    __syncthreads();

    // ---- stage B: radix-16, S=16 (in-place read/barrier/write) ----
    {
        float2 g[16];
#pragma unroll
        for (int u = 0; u < 16; u++) g[u] = zb[PIDX(t + 128*u)];
        r16_bfly(g);
        const int p = t >> 4, j = t & 15;
        float sn, cs;
        __sincosf((float)(2.0*M_PI/128.0) * (float)p, &sn, &cs);
        const float2 w1 = make_float2(cs, sn);
        const int ob = j + 256*p;
        __syncthreads();                       // all reads done
        zb[PIDX(ob)] = g[0];
        float2 wu = w1;
#pragma unroll
        for (int u = 1; u < 16; u++) {
            zb[PIDX(ob + 16*u)] = cmul(g[u], wu);
            wu = cmul(wu, w1);
        }
    }
    __syncthreads();

    // ---- stage C: radix-8, S=256, fused de-interleave epilogue (sign -) ----
    {
        const int b1 = t, b2 = 255 - t;
        float2 A[8], Bv[8];
#pragma unroll
        for (int u = 0; u < 8; u++) A[u]  = zb[PIDX(b1 + 256*u)];
#pragma unroll
        for (int u = 0; u < 8; u++) Bv[u] = zb[PIDX(b2 + 256*u)];
        r8_bfly(A);
        r8_bfly(Bv);
        float4* out4 = (float4*)(out + tbase + (size_t)(m0 + r) * NN);
#pragma unroll
        for (int u = 0; u < 4; u++) {
            float2 z1 = A[u], z2 = Bv[7-u];
            out4[b1 + 256*u] = make_float4(z1.x, -z2.y, z1.y, -z2.x);
            z1 = Bv[u]; z2 = A[7-u];
            out4[b2 + 256*u] = make_float4(z1.x, -z2.y, z1.y, -z2.x);
        }
    }
}

extern "C" void kernel_launch(void* const* d_in, const int* in_sizes, int n_in,
                              void* d_out, int out_size) {
    const float*  x     = (const float*)d_in[0];
    const float2* expkM = (const float2*)d_in[1];
    const float2* expkN = (const float2*)d_in[2];
    float* out = (float*)d_out;
    const int B = 2;

    float* scratch = nullptr;
    cudaGetSymbolAddress((void**)&scratch, g_scratch);

    const int smem1 = NCOLS * CSTRIDE_F * 4;   // 139392 B
    const int smem2 = 4 * CSTRIDE2_F * 4;      // 69760 B
    cudaFuncSetAttribute(idct_col_kernel,
                         cudaFuncAttributeMaxDynamicSharedMemorySize, smem1);
    cudaFuncSetAttribute(idxst_row_kernel,
                         cudaFuncAttributeMaxDynamicSharedMemorySize, smem2);

    // Pass 1: IDCT along M (columns of x) -> tiled scratch
    idct_col_kernel<<<B * 512, 1024, smem1>>>(x, expkM, scratch);

    // Pass 2: IDXST along N (rows) from tiled scratch -> row-major d_out
    idxst_row_kernel<<<B * 1024, 512, smem2>>>(scratch, expkN, out);
}

// round 8
// speedup vs baseline: 1.1348x; 1.1348x over previous
#include <cuda_runtime.h>
#include <math.h>

// Scratch: one full-size intermediate buffer (B*M*N floats = 134 MB).
#define SCRATCH_ELEMS (2ull * 4096ull * 4096ull)
__device__ float g_scratch[SCRATCH_ELEMS];

// Problem shape fixed: B=2, M=N=4096. Real-packed FFT length = 2048.
#define NN 4096
#define HH 2048

__device__ __forceinline__ float2 cadd(float2 a, float2 b){ return make_float2(a.x+b.x, a.y+b.y); }
__device__ __forceinline__ float2 csub(float2 a, float2 b){ return make_float2(a.x-b.x, a.y-b.y); }
__device__ __forceinline__ float2 cmul(float2 a, float2 b){
    return make_float2(fmaf(a.x, b.x, -a.y*b.y), fmaf(a.x, b.y, a.y*b.x));
}
__device__ __forceinline__ float2 mulip(float2 a){ return make_float2(-a.y, a.x); }  // * (+i)

// Pad one float2 every 16.
#define PIDX(a) ((a) + ((a) >> 4))
#define PBUF (HH + (HH >> 4))   // 2176 float2

// ---- 16-point inverse DFT in registers ----
__device__ __forceinline__ void r16_bfly(float2 g[16]) {
    const float C8 = 0.70710678118654752f;
    const float2 W1 = make_float2( 0.92387953251128674f,  0.38268343236508978f);
    const float2 W2 = make_float2( C8,  C8);
    const float2 W3 = make_float2( 0.38268343236508978f,  0.92387953251128674f);
    const float2 W6 = make_float2(-C8,  C8);
    const float2 W9 = make_float2(-0.92387953251128674f, -0.38268343236508978f);
    float2 c[16];
#pragma unroll
    for (int t0 = 0; t0 < 4; t0++) {
        float2 x0 = g[t0], x1 = g[t0+4], x2 = g[t0+8], x3 = g[t0+12];
        float2 s02 = cadd(x0,x2), d02 = csub(x0,x2);
        float2 s13 = cadd(x1,x3), d13 = csub(x1,x3);
        float2 id13 = mulip(d13);
        c[t0*4+0] = cadd(s02,s13);
        c[t0*4+1] = cadd(d02,id13);
        c[t0*4+2] = csub(s02,s13);
        c[t0*4+3] = csub(d02,id13);
    }
    c[5]  = cmul(c[5],  W1);
    c[6]  = cmul(c[6],  W2);
    c[7]  = cmul(c[7],  W3);
    c[9]  = cmul(c[9],  W2);
    c[10] = mulip(c[10]);
    c[11] = cmul(c[11], W6);
    c[13] = cmul(c[13], W3);
    c[14] = cmul(c[14], W6);
    c[15] = cmul(c[15], W9);
#pragma unroll
    for (int u0 = 0; u0 < 4; u0++) {
        float2 x0 = c[u0], x1 = c[4+u0], x2 = c[8+u0], x3 = c[12+u0];
        float2 s02 = cadd(x0,x2), d02 = csub(x0,x2);
        float2 s13 = cadd(x1,x3), d13 = csub(x1,x3);
        float2 id13 = mulip(d13);
        g[u0]    = cadd(s02,s13);
        g[u0+4]  = cadd(d02,id13);
        g[u0+8]  = csub(s02,s13);
        g[u0+12] = csub(d02,id13);
    }
}

// ---- 8-point inverse DFT in registers (a[u] -> B_u) ----
__device__ __forceinline__ void r8_bfly(float2 a[8]) {
    const float C8 = 0.70710678118654752f;
    float2 e0 = cadd(a[0],a[4]), e1 = cadd(a[1],a[5]);
    float2 e2 = cadd(a[2],a[6]), e3 = cadd(a[3],a[7]);
    float2 o0 = csub(a[0],a[4]), o1 = csub(a[1],a[5]);
    float2 o2 = csub(a[2],a[6]), o3 = csub(a[3],a[7]);
    o1 = make_float2(C8*(o1.x - o1.y),  C8*(o1.x + o1.y));
    o2 = mulip(o2);
    o3 = make_float2(-C8*(o3.x + o3.y), C8*(o3.x - o3.y));
    float2 t0 = cadd(e0,e2), t1 = csub(e0,e2);
    float2 t2 = cadd(e1,e3), t3 = csub(e1,e3);
    float2 it3 = mulip(t3);
    float2 u0 = cadd(o0,o2), u1 = csub(o0,o2);
    float2 u2 = cadd(o1,o3), u3 = csub(o1,o3);
    float2 iu3 = mulip(u3);
    a[0] = cadd(t0,t2);  a[4] = csub(t0,t2);
    a[2] = cadd(t1,it3); a[6] = csub(t1,it3);
    a[1] = cadd(u0,u2);  a[5] = csub(u0,u2);
    a[3] = cadd(u1,iu3); a[7] = csub(u1,iu3);
}

// ---------------------------------------------------------------------------
// Row FFT kernel: Makhoul pre-twiddle -> real-packed G (2048) -> radix
// 16/16/8 Stockham inverse FFT -> de-interleave epilogue. 128 thr, 1 row/CTA.
// MODE 0 = IDCT-II inverse, MODE 1 = IDXST.
// launch_bounds (128,5): 20 warps/SM (occupancy was the limiter at (128,4)).
// ---------------------------------------------------------------------------
template <int MODE>
__global__ __launch_bounds__(128, 5)
void dct_fft_kernel(const float* __restrict__ in,
                    const float2* __restrict__ expk,
                    float* __restrict__ out) {
    __shared__ __align__(16) float2 sX[PBUF];
    __shared__ __align__(16) float2 sY[PBUF];
    float* xs = (float*)sX;

    const int idx = threadIdx.x;
    const size_t base = (size_t)blockIdx.x * (size_t)NN;

    {
        const float4* in4 = (const float4*)(in + base);
        float4* xs4 = (float4*)xs;
#pragma unroll
        for (int i = idx; i < NN/4; i += 128) xs4[i] = in4[i];
    }
    __syncthreads();

    // Stage A: prologue + radix-16 + twiddle, write sY.
    {
        float2 g[16];
        const float2 E32 = make_float2(0.98078528040323044f, 0.19509032201612827f);
        float sn, cs;
        __sincosf((float)(2.0*M_PI/4096.0) * (float)idx, &sn, &cs);
        float2 w = make_float2(cs, sn);
#pragma unroll
        for (int t = 0; t < 16; t++) {
            const int j = idx + 128*t;
            float Xa0, Xb0, Xa1, Xb1;
            if (MODE == 0) {
                Xa0 = xs[j];
                Xb0 = (j == 0) ? 0.0f : xs[NN - j];
                Xa1 = xs[j + HH];
                Xb1 = xs[(j == 0) ? HH : (HH - j)];
            } else {
                Xa0 = (j == 0) ? 0.0f : xs[NN - j];
                Xb0 = (j == 0) ? 0.0f : xs[j];
                Xa1 = xs[(j == 0) ? HH : (HH - j)];
                Xb1 = xs[j + HH];
            }
            const float2 ea = expk[j];
            const float2 eb = expk[j + HH];
            float2 V0 = make_float2(0.5f*(Xa0*ea.x + Xb0*ea.y),
                                    0.5f*(Xa0*ea.y - Xb0*ea.x));
            float2 V1 = make_float2(0.5f*(Xa1*eb.x + Xb1*eb.y),
                                    0.5f*(Xa1*eb.y - Xb1*eb.x));
            float2 S = cadd(V0, V1);
            float2 D = csub(V0, V1);
            float2 wd = cmul(w, D);
            g[t] = make_float2(S.x - wd.y, S.y + wd.x);
            w = cmul(w, E32);
        }
        r16_bfly(g);
        __sincosf((float)(2.0*M_PI/2048.0) * (float)idx, &sn, &cs);
        const float2 w1 = make_float2(cs, sn);
        sY[PIDX(16*idx)] = g[0];
        float2 wu = w1;
#pragma unroll
        for (int u = 1; u < 16; u++) {
            sY[PIDX(16*idx + u)] = cmul(g[u], wu);
            wu = cmul(wu, w1);
        }
    }
    __syncthreads();

    // Stage B: radix-16, S=16.
    {
        float2 g[16];
#pragma unroll
        for (int t = 0; t < 16; t++) g[t] = sY[PIDX(idx + 128*t)];
        r16_bfly(g);
        const int p = idx >> 4, j = idx & 15;
        float sn, cs;
        __sincosf((float)(2.0*M_PI/128.0) * (float)p, &sn, &cs);
        const float2 w1 = make_float2(cs, sn);
        const int ob = j + 256*p;
        sX[PIDX(ob)] = g[0];
        float2 wu = w1;
#pragma unroll
        for (int u = 1; u < 16; u++) {
            sX[PIDX(ob + 16*u)] = cmul(g[u], wu);
            wu = cmul(wu, w1);
        }
    }
    __syncthreads();

    // Stage C: radix-8, S=256, fused with epilogue.
    {
        const int b1 = idx, b2 = 255 - idx;
        float2 A[8], Bv[8];
#pragma unroll
        for (int u = 0; u < 8; u++) A[u]  = sX[PIDX(b1 + 256*u)];
#pragma unroll
        for (int u = 0; u < 8; u++) Bv[u] = sX[PIDX(b2 + 256*u)];
        r8_bfly(A);
        r8_bfly(Bv);
        const float sgn = (MODE == 1) ? -1.0f : 1.0f;
        float4* out4 = (float4*)(out + base);
#pragma unroll
        for (int u = 0; u < 4; u++) {
            float2 z1 = A[u], z2 = Bv[7-u];
            out4[b1 + 256*u] = make_float4(z1.x, sgn*z2.y, z1.y, sgn*z2.x);
            z1 = Bv[u]; z2 = A[7-u];
            out4[b2 + 256*u] = make_float4(z1.x, sgn*z2.y, z1.y, sgn*z2.x);
        }
    }
}

// ---------------------------------------------------------------------------
// Batched transpose (B, R, C) -> (B, C, R): 64x64 tiles, 256 threads,
// float4 global loads AND stores.
// ---------------------------------------------------------------------------
__global__ __launch_bounds__(256)
void transpose_kernel(const float* __restrict__ in, float* __restrict__ out,
                      int R, int C) {
    __shared__ float tile[64][65];
    const int tx = threadIdx.x & 15;
    const int ty = threadIdx.x >> 4;
    const size_t off = (size_t)blockIdx.z * (size_t)R * (size_t)C;
    const int c0 = blockIdx.x * 64;
    const int r0 = blockIdx.y * 64;

#pragma unroll
    for (int k = 0; k < 4; k++) {
        const int r = ty + 16*k;
        const float4 v = *(const float4*)(in + off + (size_t)(r0 + r)*C + (c0 + 4*tx));
        tile[r][4*tx+0] = v.x;
        tile[r][4*tx+1] = v.y;
        tile[r][4*tx+2] = v.z;
        tile[r][4*tx+3] = v.w;
    }
    __syncthreads();
#pragma unroll
    for (int k = 0; k < 4; k++) {
        const int r = ty + 16*k;
        float4 v;
        v.x = tile[4*tx+0][r];
        v.y = tile[4*tx+1][r];
        v.z = tile[4*tx+2][r];
        v.w = tile[4*tx+3][r];
        *(float4*)(out + off + (size_t)(c0 + r)*R + (r0 + 4*tx)) = v;
    }
}

extern "C" void kernel_launch(void* const* d_in, const int* in_sizes, int n_in,
                              void* d_out, int out_size) {
    const float*  x     = (const float*)d_in[0];
    const float2* expkM = (const float2*)d_in[1];
    const float2* expkN = (const float2*)d_in[2];
    const int M = in_sizes[1] / 2;            // 4096
    const int N = in_sizes[2] / 2;            // 4096
    const int B = in_sizes[0] / (M * N);      // 2
    float* out = (float*)d_out;

    float* scratch = nullptr;
    cudaGetSymbolAddress((void**)&scratch, g_scratch);

    // Pass 1: IDXST along N (contiguous rows).  x -> scratch   (B, M, N)
    dct_fft_kernel<1><<<B * M, 128>>>(x, expkN, scratch);

    // Pass 2: transpose (B, M, N) -> (B, N, M).  scratch -> d_out
    {
        dim3 grid(N / 64, M / 64, B), blk(256);
        transpose_kernel<<<grid, blk>>>(scratch, out, M, N);
    }

    // Pass 3: IDCT along M (contiguous in transposed layout).  d_out -> scratch
    dct_fft_kernel<0><<<B * N, 128>>>(out, expkM, scratch);

    // Pass 4: transpose (B, N, M) -> (B, M, N).  scratch -> d_out
    {
        dim3 grid(M / 64, N / 64, B), blk(256);
        transpose_kernel<<<grid, blk>>>(scratch, out, N, M);
    }
}

// round 9
// speedup vs baseline: 1.1379x; 1.0028x over previous
#include <cuda_runtime.h>
#include <math.h>

// Scratch: one full-size intermediate buffer (B*M*N floats = 134 MB).
#define SCRATCH_ELEMS (2ull * 4096ull * 4096ull)
__device__ float g_scratch[SCRATCH_ELEMS];

// Problem shape fixed: B=2, M=N=4096. Real-packed FFT length = 2048.
#define NN 4096
#define HH 2048

// ---- packed f32x2 complex add/sub (sm_103a): 1 inst instead of 2 ----
__device__ __forceinline__ float2 cadd(float2 a, float2 b){
    unsigned long long ua, ub, ur;
    asm("mov.b64 %0, {%1,%2};" : "=l"(ua) : "f"(a.x), "f"(a.y));
    asm("mov.b64 %0, {%1,%2};" : "=l"(ub) : "f"(b.x), "f"(b.y));
    asm("add.rn.f32x2 %0, %1, %2;" : "=l"(ur) : "l"(ua), "l"(ub));
    float2 r;
    asm("mov.b64 {%0,%1}, %2;" : "=f"(r.x), "=f"(r.y) : "l"(ur));
    return r;
}
__device__ __forceinline__ float2 csub(float2 a, float2 b){
    unsigned long long ua, ub, ur;
    asm("mov.b64 %0, {%1,%2};" : "=l"(ua) : "f"(a.x), "f"(a.y));
    asm("mov.b64 %0, {%1,%2};" : "=l"(ub) : "f"(b.x), "f"(b.y));
    asm("sub.rn.f32x2 %0, %1, %2;" : "=l"(ur) : "l"(ua), "l"(ub));
    float2 r;
    asm("mov.b64 {%0,%1}, %2;" : "=f"(r.x), "=f"(r.y) : "l"(ur));
    return r;
}
__device__ __forceinline__ float2 cmul(float2 a, float2 b){
    return make_float2(fmaf(a.x, b.x, -a.y*b.y), fmaf(a.x, b.y, a.y*b.x));
}
__device__ __forceinline__ float2 mulip(float2 a){ return make_float2(-a.y, a.x); }  // * (+i)

// Pad one float2 every 16.
#define PIDX(a) ((a) + ((a) >> 4))
#define PBUF (HH + (HH >> 4))   // 2176 float2

// ---- 16-point inverse DFT in registers ----
__device__ __forceinline__ void r16_bfly(float2 g[16]) {
    const float C8 = 0.70710678118654752f;
    const float2 W1 = make_float2( 0.92387953251128674f,  0.38268343236508978f);
    const float2 W2 = make_float2( C8,  C8);
    const float2 W3 = make_float2( 0.38268343236508978f,  0.92387953251128674f);
    const float2 W6 = make_float2(-C8,  C8);
    const float2 W9 = make_float2(-0.92387953251128674f, -0.38268343236508978f);
    float2 c[16];
#pragma unroll
    for (int t0 = 0; t0 < 4; t0++) {
        float2 x0 = g[t0], x1 = g[t0+4], x2 = g[t0+8], x3 = g[t0+12];
        float2 s02 = cadd(x0,x2), d02 = csub(x0,x2);
        float2 s13 = cadd(x1,x3), d13 = csub(x1,x3);
        float2 id13 = mulip(d13);
        c[t0*4+0] = cadd(s02,s13);
        c[t0*4+1] = cadd(d02,id13);
        c[t0*4+2] = csub(s02,s13);
        c[t0*4+3] = csub(d02,id13);
    }
    c[5]  = cmul(c[5],  W1);
    c[6]  = cmul(c[6],  W2);
    c[7]  = cmul(c[7],  W3);
    c[9]  = cmul(c[9],  W2);
    c[10] = mulip(c[10]);
    c[11] = cmul(c[11], W6);
    c[13] = cmul(c[13], W3);
    c[14] = cmul(c[14], W6);
    c[15] = cmul(c[15], W9);
#pragma unroll
    for (int u0 = 0; u0 < 4; u0++) {
        float2 x0 = c[u0], x1 = c[4+u0], x2 = c[8+u0], x3 = c[12+u0];
        float2 s02 = cadd(x0,x2), d02 = csub(x0,x2);
        float2 s13 = cadd(x1,x3), d13 = csub(x1,x3);
        float2 id13 = mulip(d13);
        g[u0]    = cadd(s02,s13);
        g[u0+4]  = cadd(d02,id13);
        g[u0+8]  = csub(s02,s13);
        g[u0+12] = csub(d02,id13);
    }
}

// ---- 8-point inverse DFT in registers (a[u] -> B_u) ----
__device__ __forceinline__ void r8_bfly(float2 a[8]) {
    const float C8 = 0.70710678118654752f;
    float2 e0 = cadd(a[0],a[4]), e1 = cadd(a[1],a[5]);
    float2 e2 = cadd(a[2],a[6]), e3 = cadd(a[3],a[7]);
    float2 o0 = csub(a[0],a[4]), o1 = csub(a[1],a[5]);
    float2 o2 = csub(a[2],a[6]), o3 = csub(a[3],a[7]);
    o1 = make_float2(C8*(o1.x - o1.y),  C8*(o1.x + o1.y));
    o2 = mulip(o2);
    o3 = make_float2(-C8*(o3.x + o3.y), C8*(o3.x - o3.y));
    float2 t0 = cadd(e0,e2), t1 = csub(e0,e2);
    float2 t2 = cadd(e1,e3), t3 = csub(e1,e3);
    float2 it3 = mulip(t3);
    float2 u0 = cadd(o0,o2), u1 = csub(o0,o2);
    float2 u2 = cadd(o1,o3), u3 = csub(o1,o3);
    float2 iu3 = mulip(u3);
    a[0] = cadd(t0,t2);  a[4] = csub(t0,t2);
    a[2] = cadd(t1,it3); a[6] = csub(t1,it3);
    a[1] = cadd(u0,u2);  a[5] = csub(u0,u2);
    a[3] = cadd(u1,iu3); a[7] = csub(u1,iu3);
}

// ---------------------------------------------------------------------------
// Row FFT kernel: Makhoul pre-twiddle -> real-packed G (2048) -> radix
// 16/16/8 Stockham inverse FFT -> de-interleave epilogue. 128 thr, 1 row/CTA.
// MODE 0 = IDCT-II inverse, MODE 1 = IDXST.
// ---------------------------------------------------------------------------
template <int MODE>
__global__ __launch_bounds__(128, 4)
void dct_fft_kernel(const float* __restrict__ in,
                    const float2* __restrict__ expk,
                    float* __restrict__ out) {
    __shared__ __align__(16) float2 sX[PBUF];
    __shared__ __align__(16) float2 sY[PBUF];
    float* xs = (float*)sX;

    const int idx = threadIdx.x;
    const size_t base = (size_t)blockIdx.x * (size_t)NN;

    {
        const float4* in4 = (const float4*)(in + base);
        float4* xs4 = (float4*)xs;
#pragma unroll
        for (int i = idx; i < NN/4; i += 128) xs4[i] = in4[i];
    }
    __syncthreads();

    // Stage A: prologue + radix-16 + twiddle, write sY.
    {
        float2 g[16];
        const float2 E32 = make_float2(0.98078528040323044f, 0.19509032201612827f);
        float sn, cs;
        __sincosf((float)(2.0*M_PI/4096.0) * (float)idx, &sn, &cs);
        float2 w = make_float2(cs, sn);
#pragma unroll
        for (int t = 0; t < 16; t++) {
            const int j = idx + 128*t;
            float Xa0, Xb0, Xa1, Xb1;
            if (MODE == 0) {
                Xa0 = xs[j];
                Xb0 = (j == 0) ? 0.0f : xs[NN - j];
                Xa1 = xs[j + HH];
                Xb1 = xs[(j == 0) ? HH : (HH - j)];
            } else {
                Xa0 = (j == 0) ? 0.0f : xs[NN - j];
                Xb0 = (j == 0) ? 0.0f : xs[j];
                Xa1 = xs[(j == 0) ? HH : (HH - j)];
                Xb1 = xs[j + HH];
            }
            const float2 ea = expk[j];
            const float2 eb = expk[j + HH];
            float2 V0 = make_float2(0.5f*(Xa0*ea.x + Xb0*ea.y),
                                    0.5f*(Xa0*ea.y - Xb0*ea.x));
            float2 V1 = make_float2(0.5f*(Xa1*eb.x + Xb1*eb.y),
                                    0.5f*(Xa1*eb.y - Xb1*eb.x));
            float2 S = cadd(V0, V1);
            float2 D = csub(V0, V1);
            float2 wd = cmul(w, D);
            g[t] = make_float2(S.x - wd.y, S.y + wd.x);
            w = cmul(w, E32);
        }
        r16_bfly(g);
        __sincosf((float)(2.0*M_PI/2048.0) * (float)idx, &sn, &cs);
        const float2 w1 = make_float2(cs, sn);
        sY[PIDX(16*idx)] = g[0];
        float2 wu = w1;
#pragma unroll
        for (int u = 1; u < 16; u++) {
            sY[PIDX(16*idx + u)] = cmul(g[u], wu);
            wu = cmul(wu, w1);
        }
    }
    __syncthreads();

    // Stage B: radix-16, S=16.
    {
        float2 g[16];
#pragma unroll
        for (int t = 0; t < 16; t++) g[t] = sY[PIDX(idx + 128*t)];
        r16_bfly(g);
        const int p = idx >> 4, j = idx & 15;
        float sn, cs;
        __sincosf((float)(2.0*M_PI/128.0) * (float)p, &sn, &cs);
        const float2 w1 = make_float2(cs, sn);
        const int ob = j + 256*p;
        sX[PIDX(ob)] = g[0];
        float2 wu = w1;
#pragma unroll
        for (int u = 1; u < 16; u++) {
            sX[PIDX(ob + 16*u)] = cmul(g[u], wu);
            wu = cmul(wu, w1);
        }
    }
    __syncthreads();

    // Stage C: radix-8, S=256, fused with epilogue.
    {
        const int b1 = idx, b2 = 255 - idx;
        float2 A[8], Bv[8];
#pragma unroll
        for (int u = 0; u < 8; u++) A[u]  = sX[PIDX(b1 + 256*u)];
#pragma unroll
        for (int u = 0; u < 8; u++) Bv[u] = sX[PIDX(b2 + 256*u)];
        r8_bfly(A);
        r8_bfly(Bv);
        const float sgn = (MODE == 1) ? -1.0f : 1.0f;
        float4* out4 = (float4*)(out + base);
#pragma unroll
        for (int u = 0; u < 4; u++) {
            float2 z1 = A[u], z2 = Bv[7-u];
            out4[b1 + 256*u] = make_float4(z1.x, sgn*z2.y, z1.y, sgn*z2.x);
            z1 = Bv[u]; z2 = A[7-u];
            out4[b2 + 256*u] = make_float4(z1.x, sgn*z2.y, z1.y, sgn*z2.x);
        }
    }
}

// ---------------------------------------------------------------------------
// Batched transpose (B, R, C) -> (B, C, R): 64x64 tiles, 256 threads,
// float4 global loads AND stores.
// ---------------------------------------------------------------------------
__global__ __launch_bounds__(256)
void transpose_kernel(const float* __restrict__ in, float* __restrict__ out,
                      int R, int C) {
    __shared__ float tile[64][65];
    const int tx = threadIdx.x & 15;
    const int ty = threadIdx.x >> 4;
    const size_t off = (size_t)blockIdx.z * (size_t)R * (size_t)C;
    const int c0 = blockIdx.x * 64;
    const int r0 = blockIdx.y * 64;

#pragma unroll
    for (int k = 0; k < 4; k++) {
        const int r = ty + 16*k;
        const float4 v = *(const float4*)(in + off + (size_t)(r0 + r)*C + (c0 + 4*tx));
        tile[r][4*tx+0] = v.x;
        tile[r][4*tx+1] = v.y;
        tile[r][4*tx+2] = v.z;
        tile[r][4*tx+3] = v.w;
    }
    __syncthreads();
#pragma unroll
    for (int k = 0; k < 4; k++) {
        const int r = ty + 16*k;
        float4 v;
        v.x = tile[4*tx+0][r];
        v.y = tile[4*tx+1][r];
        v.z = tile[4*tx+2][r];
        v.w = tile[4*tx+3][r];
        *(float4*)(out + off + (size_t)(c0 + r)*R + (r0 + 4*tx)) = v;
    }
}

extern "C" void kernel_launch(void* const* d_in, const int* in_sizes, int n_in,
                              void* d_out, int out_size) {
    const float*  x     = (const float*)d_in[0];
    const float2* expkM = (const float2*)d_in[1];
    const float2* expkN = (const float2*)d_in[2];
    const int M = in_sizes[1] / 2;            // 4096
    const int N = in_sizes[2] / 2;            // 4096
    const int B = in_sizes[0] / (M * N);      // 2
    float* out = (float*)d_out;

    float* scratch = nullptr;
    cudaGetSymbolAddress((void**)&scratch, g_scratch);

    const size_t batch_elems = (size_t)M * (size_t)N;

    // Pass 1: IDXST along N (contiguous rows). x -> scratch. Split per batch
    // so ncu's fixed capture point (-s 5) lands on the FFT kernel.
    dct_fft_kernel<1><<<M, 128>>>(x, expkN, scratch);
    dct_fft_kernel<1><<<M, 128>>>(x + batch_elems, expkN, scratch + batch_elems);

    // Pass 2: transpose (B, M, N) -> (B, N, M).  scratch -> d_out
    {
        dim3 grid(N / 64, M / 64, B), blk(256);
        transpose_kernel<<<grid, blk>>>(scratch, out, M, N);
    }

    // Pass 3: IDCT along M (contiguous in transposed layout).  d_out -> scratch
    dct_fft_kernel<0><<<B * N, 128>>>(out, expkM, scratch);

    // Pass 4: transpose (B, N, M) -> (B, M, N).  scratch -> d_out
    {
        dim3 grid(M / 64, N / 64, B), blk(256);
        transpose_kernel<<<grid, blk>>>(scratch, out, N, M);
    }
}

// round 10
// speedup vs baseline: 1.1956x; 1.0507x over previous
#include <cuda_runtime.h>
#include <math.h>

// Scratch: one full-size intermediate buffer (B*M*N floats = 134 MB).
#define SCRATCH_ELEMS (2ull * 4096ull * 4096ull)
__device__ float g_scratch[SCRATCH_ELEMS];

// Problem shape fixed: B=2, M=N=4096. Real-packed FFT length = 2048.
#define NN 4096
#define HH 2048

// ---- packed f32x2 complex add/sub (sm_103a) ----
__device__ __forceinline__ float2 cadd(float2 a, float2 b){
    unsigned long long ua, ub, ur;
    asm("mov.b64 %0, {%1,%2};" : "=l"(ua) : "f"(a.x), "f"(a.y));
    asm("mov.b64 %0, {%1,%2};" : "=l"(ub) : "f"(b.x), "f"(b.y));
    asm("add.rn.f32x2 %0, %1, %2;" : "=l"(ur) : "l"(ua), "l"(ub));
    float2 r;
    asm("mov.b64 {%0,%1}, %2;" : "=f"(r.x), "=f"(r.y) : "l"(ur));
    return r;
}
__device__ __forceinline__ float2 csub(float2 a, float2 b){
    unsigned long long ua, ub, ur;
    asm("mov.b64 %0, {%1,%2};" : "=l"(ua) : "f"(a.x), "f"(a.y));
    asm("mov.b64 %0, {%1,%2};" : "=l"(ub) : "f"(b.x), "f"(b.y));
    asm("sub.rn.f32x2 %0, %1, %2;" : "=l"(ur) : "l"(ua), "l"(ub));
    float2 r;
    asm("mov.b64 {%0,%1}, %2;" : "=f"(r.x), "=f"(r.y) : "l"(ur));
    return r;
}
__device__ __forceinline__ float2 cmul(float2 a, float2 b){
    return make_float2(fmaf(a.x, b.x, -a.y*b.y), fmaf(a.x, b.y, a.y*b.x));
}
__device__ __forceinline__ float2 mulip(float2 a){ return make_float2(-a.y, a.x); }  // * (+i)

// Pad one float2 every 16.
#define PIDX(a) ((a) + ((a) >> 4))
#define PBUF (HH + (HH >> 4))   // 2176 float2

// ---- 16-point inverse DFT in registers ----
__device__ __forceinline__ void r16_bfly(float2 g[16]) {
    const float C8 = 0.70710678118654752f;
    const float2 W1 = make_float2( 0.92387953251128674f,  0.38268343236508978f);
    const float2 W2 = make_float2( C8,  C8);
    const float2 W3 = make_float2( 0.38268343236508978f,  0.92387953251128674f);
    const float2 W6 = make_float2(-C8,  C8);
    const float2 W9 = make_float2(-0.92387953251128674f, -0.38268343236508978f);
    float2 c[16];
#pragma unroll
    for (int t0 = 0; t0 < 4; t0++) {
        float2 x0 = g[t0], x1 = g[t0+4], x2 = g[t0+8], x3 = g[t0+12];
        float2 s02 = cadd(x0,x2), d02 = csub(x0,x2);
        float2 s13 = cadd(x1,x3), d13 = csub(x1,x3);
        float2 id13 = mulip(d13);
        c[t0*4+0] = cadd(s02,s13);
        c[t0*4+1] = cadd(d02,id13);
        c[t0*4+2] = csub(s02,s13);
        c[t0*4+3] = csub(d02,id13);
    }
    c[5]  = cmul(c[5],  W1);
    c[6]  = cmul(c[6],  W2);
    c[7]  = cmul(c[7],  W3);
    c[9]  = cmul(c[9],  W2);
    c[10] = mulip(c[10]);
    c[11] = cmul(c[11], W6);
    c[13] = cmul(c[13], W3);
    c[14] = cmul(c[14], W6);
    c[15] = cmul(c[15], W9);
#pragma unroll
    for (int u0 = 0; u0 < 4; u0++) {
        float2 x0 = c[u0], x1 = c[4+u0], x2 = c[8+u0], x3 = c[12+u0];
        float2 s02 = cadd(x0,x2), d02 = csub(x0,x2);
        float2 s13 = cadd(x1,x3), d13 = csub(x1,x3);
        float2 id13 = mulip(d13);
        g[u0]    = cadd(s02,s13);
        g[u0+4]  = cadd(d02,id13);
        g[u0+8]  = csub(s02,s13);
        g[u0+12] = csub(d02,id13);
    }
}

// ---- 8-point inverse DFT in registers (a[u] -> B_u) ----
__device__ __forceinline__ void r8_bfly(float2 a[8]) {
    const float C8 = 0.70710678118654752f;
    float2 e0 = cadd(a[0],a[4]), e1 = cadd(a[1],a[5]);
    float2 e2 = cadd(a[2],a[6]), e3 = cadd(a[3],a[7]);
    float2 o0 = csub(a[0],a[4]), o1 = csub(a[1],a[5]);
    float2 o2 = csub(a[2],a[6]), o3 = csub(a[3],a[7]);
    o1 = make_float2(C8*(o1.x - o1.y),  C8*(o1.x + o1.y));
    o2 = mulip(o2);
    o3 = make_float2(-C8*(o3.x + o3.y), C8*(o3.x - o3.y));
    float2 t0 = cadd(e0,e2), t1 = csub(e0,e2);
    float2 t2 = cadd(e1,e3), t3 = csub(e1,e3);
    float2 it3 = mulip(t3);
    float2 u0 = cadd(o0,o2), u1 = csub(o0,o2);
    float2 u2 = cadd(o1,o3), u3 = csub(o1,o3);
    float2 iu3 = mulip(u3);
    a[0] = cadd(t0,t2);  a[4] = csub(t0,t2);
    a[2] = cadd(t1,it3); a[6] = csub(t1,it3);
    a[1] = cadd(u0,u2);  a[5] = csub(u0,u2);
    a[3] = cadd(u1,iu3); a[7] = csub(u1,iu3);
}

// ---------------------------------------------------------------------------
// Row FFT kernel: Makhoul pre-twiddle -> real-packed G (2048) -> radix
// 16/16/8 Stockham inverse FFT -> de-interleave epilogue. 128 thr, 1 row/CTA.
// MODE 0 = IDCT-II inverse, MODE 1 = IDXST.
// ---------------------------------------------------------------------------
template <int MODE>
__global__ __launch_bounds__(128, 4)
void dct_fft_kernel(const float* __restrict__ in,
                    const float2* __restrict__ expk,
                    float* __restrict__ out) {
    __shared__ __align__(16) float2 sX[PBUF];
    __shared__ __align__(16) float2 sY[PBUF];
    float* xs = (float*)sX;

    const int idx = threadIdx.x;
    const size_t base = (size_t)blockIdx.x * (size_t)NN;

    {
        const float4* in4 = (const float4*)(in + base);
        float4* xs4 = (float4*)xs;
#pragma unroll
        for (int i = idx; i < NN/4; i += 128) xs4[i] = in4[i];
    }
    __syncthreads();

    // Stage A: prologue + radix-16 + twiddle, write sY.
    {
        float2 g[16];
        const float2 E32 = make_float2(0.98078528040323044f, 0.19509032201612827f);
        float sn, cs;
        __sincosf((float)(2.0*M_PI/4096.0) * (float)idx, &sn, &cs);
        float2 w = make_float2(cs, sn);
#pragma unroll
        for (int t = 0; t < 16; t++) {
            const int j = idx + 128*t;
            float Xa0, Xb0, Xa1, Xb1;
            if (MODE == 0) {
                Xa0 = xs[j];
                Xb0 = (j == 0) ? 0.0f : xs[NN - j];
                Xa1 = xs[j + HH];
                Xb1 = xs[(j == 0) ? HH : (HH - j)];
            } else {
                Xa0 = (j == 0) ? 0.0f : xs[NN - j];
                Xb0 = (j == 0) ? 0.0f : xs[j];
                Xa1 = xs[(j == 0) ? HH : (HH - j)];
                Xb1 = xs[j + HH];
            }
            const float2 ea = expk[j];
            const float2 eb = expk[j + HH];
            float2 V0 = make_float2(0.5f*(Xa0*ea.x + Xb0*ea.y),
                                    0.5f*(Xa0*ea.y - Xb0*ea.x));
            float2 V1 = make_float2(0.5f*(Xa1*eb.x + Xb1*eb.y),
                                    0.5f*(Xa1*eb.y - Xb1*eb.x));
            float2 S = cadd(V0, V1);
            float2 D = csub(V0, V1);
            float2 wd = cmul(w, D);
            g[t] = make_float2(S.x - wd.y, S.y + wd.x);
            w = cmul(w, E32);
        }
        r16_bfly(g);
        __sincosf((float)(2.0*M_PI/2048.0) * (float)idx, &sn, &cs);
        const float2 w1 = make_float2(cs, sn);
        sY[PIDX(16*idx)] = g[0];
        float2 wu = w1;
#pragma unroll
        for (int u = 1; u < 16; u++) {
            sY[PIDX(16*idx + u)] = cmul(g[u], wu);
            wu = cmul(wu, w1);
        }
    }
    __syncthreads();

    // Stage B: radix-16, S=16.
    {
        float2 g[16];
#pragma unroll
        for (int t = 0; t < 16; t++) g[t] = sY[PIDX(idx + 128*t)];
        r16_bfly(g);
        const int p = idx >> 4, j = idx & 15;
        float sn, cs;
        __sincosf((float)(2.0*M_PI/128.0) * (float)p, &sn, &cs);
        const float2 w1 = make_float2(cs, sn);
        const int ob = j + 256*p;
        sX[PIDX(ob)] = g[0];
        float2 wu = w1;
#pragma unroll
        for (int u = 1; u < 16; u++) {
            sX[PIDX(ob + 16*u)] = cmul(g[u], wu);
            wu = cmul(wu, w1);
        }
    }
    __syncthreads();

    // Stage C: radix-8, S=256, fused with epilogue.
    {
        const int b1 = idx, b2 = 255 - idx;
        float2 A[8], Bv[8];
#pragma unroll
        for (int u = 0; u < 8; u++) A[u]  = sX[PIDX(b1 + 256*u)];
#pragma unroll
        for (int u = 0; u < 8; u++) Bv[u] = sX[PIDX(b2 + 256*u)];
        r8_bfly(A);
        r8_bfly(Bv);
        const float sgn = (MODE == 1) ? -1.0f : 1.0f;
        float4* out4 = (float4*)(out + base);
#pragma unroll
        for (int u = 0; u < 4; u++) {
            float2 z1 = A[u], z2 = Bv[7-u];
            out4[b1 + 256*u] = make_float4(z1.x, sgn*z2.y, z1.y, sgn*z2.x);
            z1 = Bv[u]; z2 = A[7-u];
            out4[b2 + 256*u] = make_float4(z1.x, sgn*z2.y, z1.y, sgn*z2.x);
        }
    }
}

// ---------------------------------------------------------------------------
// Single-batch transpose R x C -> C x R: 64x64 tiles, 256 threads, float4.
// ---------------------------------------------------------------------------
__global__ __launch_bounds__(256)
void transpose_kernel(const float* __restrict__ in, float* __restrict__ out,
                      int R, int C) {
    __shared__ float tile[64][65];
    const int tx = threadIdx.x & 15;
    const int ty = threadIdx.x >> 4;
    const int c0 = blockIdx.x * 64;
    const int r0 = blockIdx.y * 64;

#pragma unroll
    for (int k = 0; k < 4; k++) {
        const int r = ty + 16*k;
        const float4 v = *(const float4*)(in + (size_t)(r0 + r)*C + (c0 + 4*tx));
        tile[r][4*tx+0] = v.x;
        tile[r][4*tx+1] = v.y;
        tile[r][4*tx+2] = v.z;
        tile[r][4*tx+3] = v.w;
    }
    __syncthreads();
#pragma unroll
    for (int k = 0; k < 4; k++) {
        const int r = ty + 16*k;
        float4 v;
        v.x = tile[4*tx+0][r];
        v.y = tile[4*tx+1][r];
        v.z = tile[4*tx+2][r];
        v.w = tile[4*tx+3][r];
        *(float4*)(out + (size_t)(c0 + r)*R + (r0 + 4*tx)) = v;
    }
}

// One-time host resources (handles only; launched work is identical per call).
static cudaStream_t g_s1;
static cudaEvent_t  g_e_fork, g_e_join;
static bool         g_init_done = false;

static void ensure_init() {
    if (!g_init_done) {
        cudaStreamCreateWithFlags(&g_s1, cudaStreamNonBlocking);
        cudaEventCreateWithFlags(&g_e_fork, cudaEventDisableTiming);
        cudaEventCreateWithFlags(&g_e_join, cudaEventDisableTiming);
        g_init_done = true;
    }
}

extern "C" void kernel_launch(void* const* d_in, const int* in_sizes, int n_in,
                              void* d_out, int out_size) {
    const float*  x     = (const float*)d_in[0];
    const float2* expkM = (const float2*)d_in[1];
    const float2* expkN = (const float2*)d_in[2];
    const int M = in_sizes[1] / 2;            // 4096
    const int N = in_sizes[2] / 2;            // 4096
    float* out = (float*)d_out;

    ensure_init();

    float* scratch = nullptr;
    cudaGetSymbolAddress((void**)&scratch, g_scratch);

    const size_t be = (size_t)M * (size_t)N;  // elements per batch
    dim3 tgrid(N / 64, M / 64), tblk(256);

    // ---- batch 0 pipeline on stream 0 (the capturing stream) ----
    dct_fft_kernel<1><<<M, 128, 0, 0>>>(x, expkN, scratch);

    // Fork: batch 1 starts its FFT only after batch 0's first FFT finishes,
    // so one stream runs L1-bound FFTs while the other runs DRAM-bound
    // transposes for the rest of the pipeline.
    cudaEventRecord(g_e_fork, 0);
    cudaStreamWaitEvent(g_s1, g_e_fork, 0);

    // batch 1 pipeline on s1
    dct_fft_kernel<1><<<M, 128, 0, g_s1>>>(x + be, expkN, scratch + be);
    transpose_kernel<<<tgrid, tblk, 0, g_s1>>>(scratch + be, out + be, M, N);
    dct_fft_kernel<0><<<N, 128, 0, g_s1>>>(out + be, expkM, scratch + be);
    transpose_kernel<<<tgrid, tblk, 0, g_s1>>>(scratch + be, out + be, N, M);
    cudaEventRecord(g_e_join, g_s1);

    // rest of batch 0 pipeline on stream 0
    transpose_kernel<<<tgrid, tblk, 0, 0>>>(scratch, out, M, N);
    dct_fft_kernel<0><<<N, 128, 0, 0>>>(out, expkM, scratch);
    transpose_kernel<<<tgrid, tblk, 0, 0>>>(scratch, out, N, M);

    // Join: stream 0 (capture stream) waits for batch 1 completion.
    cudaStreamWaitEvent(0, g_e_join, 0);
}